// round 6
// baseline (speedup 1.0000x reference)
#include <cuda_runtime.h>
#include <cstdint>

#define DIM    256
#define NQ     8
#define FFN    2048
#define EMBED  512
#define BS     32768                    // B * S
#define TOTAL_F4 (BS * EMBED / 4)       // 4,194,304 float4
#define GRID   592                      // 4 CTAs/SM -> guaranteed co-resident
#define CCTAS  64                       // compute CTAs (8 warps -> 8 e's each)

// Scratch / sync (device globals — allocation-free per harness rules)
__device__ float g_o[EMBED];
__device__ int   g_flag = 0;   // compute-done arrivals
__device__ int   g_done = 0;   // broadcast-done arrivals (for reset)

__global__ void __launch_bounds__(256, 4)
k_all(const float* __restrict__ U_re,
      const float* __restrict__ U_im,
      const float* __restrict__ W1,
      const float* __restrict__ b1,
      const float* __restrict__ W2,
      const float* __restrict__ b2,
      float4* __restrict__ out)
{
    __shared__ float  sp[DIM];          // probabilities
    __shared__ float  sz[NQ];           // z vector
    __shared__ float4 sh4[FFN / 4];     // full h (8 KB); first 128 reused as row buf

    const int t    = threadIdx.x;       // 0..255
    const int lane = t & 31;
    const int warp = t >> 5;            // 0..7
    const int bid  = blockIdx.x;

    // ================= compute phase: CTAs 0..63 =================
    if (bid < CCTAS) {
        // p_t = |U[t,0]|^2  (row stride DIM)
        {
            const float re = __ldg(&U_re[t * DIM]);
            const float im = __ldg(&U_im[t * DIM]);
            sp[t] = re * re + im * im;
        }
        __syncthreads();

        // warp q reduces qubit q: sign flips on bit (7-q) of state index s
        {
            const int bit = (NQ - 1) - warp;
            float v = 0.f;
            #pragma unroll
            for (int j = 0; j < 8; ++j) {
                const int s = lane + 32 * j;
                const float pv = sp[s];
                v += ((s >> bit) & 1) ? -pv : pv;
            }
            #pragma unroll
            for (int off = 16; off > 0; off >>= 1)
                v += __shfl_xor_sync(0xFFFFFFFFu, v, off);
            if (lane == 0) sz[warp] = v;
        }
        __syncthreads();

        const float z0 = sz[0], z1 = sz[1], z2 = sz[2], z3 = sz[3];
        const float z4 = sz[4], z5 = sz[5], z6 = sz[6], z7 = sz[7];

        // h rows t*8 .. t*8+7   (W1 is (FFN, 8) row-major)
        {
            const float4* __restrict__ w1v = (const float4*)(W1 + t * 8 * NQ);
            const float4 bb0 = __ldg((const float4*)(b1 + t * 8));
            const float4 bb1 = __ldg((const float4*)(b1 + t * 8 + 4));
            const float bias[8] = { bb0.x, bb0.y, bb0.z, bb0.w,
                                    bb1.x, bb1.y, bb1.z, bb1.w };
            float hv[8];
            #pragma unroll
            for (int k = 0; k < 8; ++k) {
                const float4 a = __ldg(&w1v[k * 2]);
                const float4 b = __ldg(&w1v[k * 2 + 1]);
                float acc = bias[k];
                acc += z0*a.x + z1*a.y + z2*a.z + z3*a.w;
                acc += z4*b.x + z5*b.y + z6*b.z + z7*b.w;
                hv[k] = fmaxf(acc, 0.f);
            }
            sh4[t * 2]     = make_float4(hv[0], hv[1], hv[2], hv[3]);
            sh4[t * 2 + 1] = make_float4(hv[4], hv[5], hv[6], hv[7]);
        }
        __syncthreads();

        // o[e]: warp w -> e = bid*8 + w
        const int e = bid * 8 + warp;
        const float4* __restrict__ w2v = (const float4*)(W2 + (size_t)e * FFN);
        float acc = 0.f;
        #pragma unroll
        for (int i = lane; i < FFN / 4; i += 32) {
            const float4 w = __ldg(&w2v[i]);
            const float4 h = sh4[i];
            acc += w.x*h.x + w.y*h.y + w.z*h.z + w.w*h.w;
        }
        #pragma unroll
        for (int off = 16; off > 0; off >>= 1)
            acc += __shfl_xor_sync(0xFFFFFFFFu, acc, off);
        if (lane == 0) g_o[e] = acc + __ldg(&b2[e]);

        // publish: make g_o visible, then arrive
        __syncthreads();
        if (t == 0) {
            __threadfence();
            atomicAdd(&g_flag, 1);
        }
    }

    // ================= handoff: wait for all 64 compute CTAs =================
    if (t == 0) {
        while (atomicAdd(&g_flag, 0) < CCTAS)
            __nanosleep(128);
    }
    __syncthreads();
    __threadfence();   // order the flag observation before g_o reads

    // ================= broadcast phase: all CTAs =================
    // row into smem (reuse sh4's first 128 slots), L2-coherent loads
    if (t < EMBED / 4) {
        const float* go = (const float*)g_o;
        float4 v;
        v.x = __ldcg(go + t * 4 + 0);
        v.y = __ldcg(go + t * 4 + 1);
        v.z = __ldcg(go + t * 4 + 2);
        v.w = __ldcg(go + t * 4 + 3);
        sh4[t] = v;
    }
    __syncthreads();

    unsigned idx = bid * 256u + t;
    const unsigned stride = GRID * 256u;          // multiple of 128
    const float4 v = sh4[idx & (EMBED / 4 - 1)];  // column loop-invariant

    for (; idx < TOTAL_F4; idx += stride)
        out[idx] = v;

    // ================= reset for next graph replay =================
    __syncthreads();
    if (t == 0) {
        const int n = atomicAdd(&g_done, 1);
        if (n == GRID - 1) {     // last CTA out resets both flags
            g_done = 0;
            g_flag = 0;
            __threadfence();
        }
    }
}

// ---------------------------------------------------------------------------
extern "C" void kernel_launch(void* const* d_in, const int* in_sizes, int n_in,
                              void* d_out, int out_size)
{
    // metadata order: x, U_re, U_im, W1, b1, W2, b2  (x unused by the math)
    const float* U_re = (const float*)d_in[1];
    const float* U_im = (const float*)d_in[2];
    const float* W1   = (const float*)d_in[3];
    const float* b1   = (const float*)d_in[4];
    const float* W2   = (const float*)d_in[5];
    const float* b2   = (const float*)d_in[6];
    float*       out  = (float*)d_out;

    k_all<<<GRID, 256>>>(U_re, U_im, W1, b1, W2, b2, (float4*)out);
}

// round 7
// speedup vs baseline: 1.1081x; 1.1081x over previous
#include <cuda_runtime.h>
#include <cstdint>

#define DIM    256
#define NQ     8
#define FFN    2048
#define EMBED  512
#define BS     32768                    // B * S
#define TOTAL_F4 (BS * EMBED / 4)       // 4,194,304 float4
#define BCAST_CTAS 1184                 // 148 SMs x 8

// Scratch (device global — allocation-free per harness rules)
__device__ float g_o[EMBED];

// ---------------------------------------------------------------------------
// Kernel A: z (per-warp parallel reduce) -> h (smem) -> o[e] per warp.
// 64 CTAs x 256 threads; CTA b owns e = b*8 .. b*8+7.
// Fires the PDL trigger right after its g_o contribution is stored.
// ---------------------------------------------------------------------------
__global__ void k_fused_h_o(const float* __restrict__ U_re,
                            const float* __restrict__ U_im,
                            const float* __restrict__ W1,
                            const float* __restrict__ b1,
                            const float* __restrict__ W2,
                            const float* __restrict__ b2)
{
    __shared__ float  sp[DIM];         // probabilities
    __shared__ float  sz[NQ];          // z vector
    __shared__ float4 sh4[FFN / 4];    // full h, 8 KB

    const int t    = threadIdx.x;      // 0..255
    const int lane = t & 31;
    const int warp = t >> 5;           // 0..7

    // p_t = |U[t,0]|^2  (row stride DIM)
    {
        const float re = __ldg(&U_re[t * DIM]);
        const float im = __ldg(&U_im[t * DIM]);
        sp[t] = re * re + im * im;
    }
    __syncthreads();

    // warp q reduces qubit q: sign flips on bit (7-q) of state index s
    {
        const int bit = (NQ - 1) - warp;
        float v = 0.f;
        #pragma unroll
        for (int j = 0; j < 8; ++j) {
            const int s = lane + 32 * j;
            const float pv = sp[s];
            v += ((s >> bit) & 1) ? -pv : pv;
        }
        #pragma unroll
        for (int off = 16; off > 0; off >>= 1)
            v += __shfl_xor_sync(0xFFFFFFFFu, v, off);
        if (lane == 0) sz[warp] = v;
    }
    __syncthreads();

    const float z0 = sz[0], z1 = sz[1], z2 = sz[2], z3 = sz[3];
    const float z4 = sz[4], z5 = sz[5], z6 = sz[6], z7 = sz[7];

    // h rows t*8 .. t*8+7   (W1 is (FFN, 8) row-major)
    {
        const float4* __restrict__ w1v = (const float4*)(W1 + t * 8 * NQ);
        const float4 bb0 = __ldg((const float4*)(b1 + t * 8));
        const float4 bb1 = __ldg((const float4*)(b1 + t * 8 + 4));
        const float bias[8] = { bb0.x, bb0.y, bb0.z, bb0.w,
                                bb1.x, bb1.y, bb1.z, bb1.w };
        float hv[8];
        #pragma unroll
        for (int k = 0; k < 8; ++k) {
            const float4 a = __ldg(&w1v[k * 2]);
            const float4 b = __ldg(&w1v[k * 2 + 1]);
            float acc = bias[k];
            acc += z0*a.x + z1*a.y + z2*a.z + z3*a.w;
            acc += z4*b.x + z5*b.y + z6*b.z + z7*b.w;
            hv[k] = fmaxf(acc, 0.f);
        }
        sh4[t * 2]     = make_float4(hv[0], hv[1], hv[2], hv[3]);
        sh4[t * 2 + 1] = make_float4(hv[4], hv[5], hv[6], hv[7]);
    }
    __syncthreads();

    // o[e]: warp w -> e = blockIdx*8 + w
    const int e = blockIdx.x * 8 + warp;
    const float4* __restrict__ w2v = (const float4*)(W2 + (size_t)e * FFN);

    float acc = 0.f;
    #pragma unroll
    for (int i = lane; i < FFN / 4; i += 32) {
        const float4 w = __ldg(&w2v[i]);
        const float4 h = sh4[i];
        acc += w.x*h.x + w.y*h.y + w.z*h.z + w.w*h.w;
    }
    #pragma unroll
    for (int off = 16; off > 0; off >>= 1)
        acc += __shfl_xor_sync(0xFFFFFFFFu, acc, off);

    if (lane == 0) g_o[e] = acc + __ldg(&b2[e]);

    // PDL: this CTA's contribution is done — allow the broadcast grid in.
    cudaTriggerProgrammaticLaunchCompletion();
}

// ---------------------------------------------------------------------------
// Kernel B: broadcast o[512] into out. Launched with PDL: CTAs come up while
// kernel A still runs, do setup, then wait on the grid dependency.
// ---------------------------------------------------------------------------
__global__ void __launch_bounds__(256)
k_broadcast(float4* __restrict__ out)
{
    __shared__ float4 so[EMBED / 4];

    // address setup before the dependency wait (overlapped with kernel A)
    unsigned idx = blockIdx.x * 256u + threadIdx.x;
    const unsigned stride = BCAST_CTAS * 256u;      // multiple of 128

    // wait until kernel A (and its memory) is fully visible
    cudaGridDependencySynchronize();

    if (threadIdx.x < EMBED / 4)
        so[threadIdx.x] = ((const float4*)g_o)[threadIdx.x];
    __syncthreads();

    const float4 v = so[idx & (EMBED / 4 - 1)];     // column loop-invariant

    #pragma unroll 2
    for (; idx < TOTAL_F4; idx += stride)
        out[idx] = v;
}

// ---------------------------------------------------------------------------
extern "C" void kernel_launch(void* const* d_in, const int* in_sizes, int n_in,
                              void* d_out, int out_size)
{
    // metadata order: x, U_re, U_im, W1, b1, W2, b2  (x unused by the math)
    const float* U_re = (const float*)d_in[1];
    const float* U_im = (const float*)d_in[2];
    const float* W1   = (const float*)d_in[3];
    const float* b1   = (const float*)d_in[4];
    const float* W2   = (const float*)d_in[5];
    const float* b2   = (const float*)d_in[6];
    float*       out  = (float*)d_out;

    k_fused_h_o<<<EMBED / 8, 256>>>(U_re, U_im, W1, b1, W2, b2);

    // Broadcast with programmatic dependent launch on the same stream.
    cudaLaunchConfig_t cfg = {};
    cfg.gridDim  = dim3(BCAST_CTAS);
    cfg.blockDim = dim3(256);
    cfg.dynamicSmemBytes = 0;
    cfg.stream = 0;  // legacy default stream (same one the harness captures)

    cudaLaunchAttribute attr[1];
    attr[0].id = cudaLaunchAttributeProgrammaticStreamSerialization;
    attr[0].val.programmaticStreamSerializationAllowed = 1;
    cfg.attrs = attr;
    cfg.numAttrs = 1;

    float4* outv = (float4*)out;
    cudaLaunchKernelEx(&cfg, k_broadcast, outv);
}